// round 14
// baseline (speedup 1.0000x reference)
#include <cuda_runtime.h>
#include <cuda_bf16.h>
#include <cuda_fp16.h>
#include <math.h>
#include <stdint.h>

#define BATCH 4
#define T 4096
#define C 768
#define H 64
#define M_TOT (BATCH * T)

// work-balanced split-K: fixed 512-key chunks, up to 8 per query tile
#define NCHUNK 8
#define CHUNK_KEYS 512

// W (and hence q,k,v) are pre-scaled by 64.  Scores: s' = q'·k' = 4096·q·k.
// softmax exponent = s' · SC2;  |exponent| <~ 1, so no max-subtraction.
#define SC2 4.40275588e-5f        // 0.125 * log2(e) / 4096
#define INV_VSCALE 0.015625f      // 1/64 (undo V scaling in combine)

// ---- pre-converted operand arrays (fp16 throughout the fast path) ----
__device__ __align__(16) __half g_xf[(size_t)M_TOT * C];      // x, single fp16
__device__ __align__(16) __half g_Whi[3 * C * H];             // 64*W hi
__device__ __align__(16) __half g_Wlo[3 * C * H];             // 64*W lo
__device__ __align__(16) __half g_Qf [M_TOT * H];             // q' single fp16
__device__ __align__(16) __half g_Khi[M_TOT * H];             // k' hi
__device__ __align__(16) __half g_Klo[M_TOT * H];             // k' lo
__device__ __align__(16) __half g_Vhi[M_TOT * H];             // v' hi
__device__ __align__(16) __half g_Vlo[M_TOT * H];             // v' lo
__device__ float g_l[(size_t)M_TOT * NCHUNK];
__device__ float g_acc[(size_t)M_TOT * NCHUNK * H];

// ============================================================================
// Primitives
// ============================================================================
__device__ __forceinline__ uint32_t smem_to_u32(const void* smem_ptr) {
    uint32_t addr;
    asm("{ .reg .u64 tmp; cvta.to.shared.u64 tmp, %1; cvt.u32.u64 %0, tmp; }"
        : "=r"(addr) : "l"(smem_ptr));
    return addr;
}

// fp16 MMA: D(16x8,f32) += A(16x16,f16) * B(16x8,f16)
__device__ __forceinline__ void mma16816h(float* d, const uint32_t* a, const uint32_t* b) {
    asm volatile(
        "mma.sync.aligned.m16n8k16.row.col.f32.f16.f16.f32 "
        "{%0,%1,%2,%3}, {%4,%5,%6,%7}, {%8,%9}, {%0,%1,%2,%3};"
        : "+f"(d[0]), "+f"(d[1]), "+f"(d[2]), "+f"(d[3])
        : "r"(a[0]), "r"(a[1]), "r"(a[2]), "r"(a[3]), "r"(b[0]), "r"(b[1]));
}

__device__ __forceinline__ void ldsm_x4(uint32_t* r, uint32_t a) {
    asm volatile("ldmatrix.sync.aligned.m8n8.x4.shared.b16 {%0,%1,%2,%3}, [%4];"
        : "=r"(r[0]), "=r"(r[1]), "=r"(r[2]), "=r"(r[3]) : "r"(a));
}

__device__ __forceinline__ void ldsm_x4_t(uint32_t* r, uint32_t a) {
    asm volatile("ldmatrix.sync.aligned.m8n8.x4.trans.shared.b16 {%0,%1,%2,%3}, [%4];"
        : "=r"(r[0]), "=r"(r[1]), "=r"(r[2]), "=r"(r[3]) : "r"(a));
}

#define CP16(dst, src) \
    asm volatile("cp.async.cg.shared.global [%0], [%1], 16;" \
                 :: "r"(dst), "l"(src) : "memory")
#define CP_COMMIT() asm volatile("cp.async.commit_group;" ::: "memory")
#define CP_WAIT0()  asm volatile("cp.async.wait_group 0;" ::: "memory")
#define CP_WAIT1()  asm volatile("cp.async.wait_group 1;" ::: "memory")

__device__ __forceinline__ void cvt_f16_hilo(float vx, float vy, uint32_t& hi, uint32_t& lo) {
    __half2 h = __floats2half2_rn(vx, vy);
    hi = *reinterpret_cast<uint32_t*>(&h);
    float rx = vx - __half2float(__low2half(h));
    float ry = vy - __half2float(__high2half(h));
    __half2 l2 = __floats2half2_rn(rx, ry);
    lo = *reinterpret_cast<uint32_t*>(&l2);
}

// SMEM tile: 64 rows x 64 f16 in 144B-stride rows (conflict-free ldmatrix)
#define SKB 144
#define TILE_BYTES (64 * SKB)             // 9216
#define QKV_SLOT (3 * TILE_BYTES)         // xf16 | Whi | Wlo = 27648
#define QKV_SMEM (2 * QKV_SLOT)           // 55296 (2-stage)
#define KV_SLOT (4 * TILE_BYTES)          // Khi|Klo|Vhi|Vlo = 36864
#define FLASH_SMEM (2 * KV_SLOT)          // 73728 (2-stage; 3 CTAs/SM)

// ---------------------------------------------------------------------------
// Prep kernels
// ---------------------------------------------------------------------------
__global__ __launch_bounds__(256) void prep_x_kernel(const float* __restrict__ x)
{
    size_t i = ((size_t)blockIdx.x * 256 + threadIdx.x) * 8;
    float4 a = *(const float4*)(x + i);
    float4 b = *(const float4*)(x + i + 4);
    __half2 h0 = __floats2half2_rn(a.x, a.y);
    __half2 h1 = __floats2half2_rn(a.z, a.w);
    __half2 h2 = __floats2half2_rn(b.x, b.y);
    __half2 h3 = __floats2half2_rn(b.z, b.w);
    *(uint4*)(g_xf + i) = make_uint4(
        *reinterpret_cast<uint32_t*>(&h0), *reinterpret_cast<uint32_t*>(&h1),
        *reinterpret_cast<uint32_t*>(&h2), *reinterpret_cast<uint32_t*>(&h3));
}

__global__ __launch_bounds__(256) void prep_w_kernel(
    const float* __restrict__ Wq, const float* __restrict__ Wk,
    const float* __restrict__ Wv)
{
    size_t i = ((size_t)blockIdx.x * 256 + threadIdx.x) * 8;
    int which = (int)(i / (C * H));
    const float* W = (which == 0) ? Wq : (which == 1) ? Wk : Wv;
    size_t local = i - (size_t)which * (C * H);
    float4 a = *(const float4*)(W + local);
    float4 b = *(const float4*)(W + local + 4);
    // scale by 64 (exact) so the f16 residual (lo) stays in normal range
    uint32_t h[4], l[4];
    cvt_f16_hilo(a.x * 64.0f, a.y * 64.0f, h[0], l[0]);
    cvt_f16_hilo(a.z * 64.0f, a.w * 64.0f, h[1], l[1]);
    cvt_f16_hilo(b.x * 64.0f, b.y * 64.0f, h[2], l[2]);
    cvt_f16_hilo(b.z * 64.0f, b.w * 64.0f, h[3], l[3]);
    *(uint4*)(g_Whi + i) = make_uint4(h[0], h[1], h[2], h[3]);
    *(uint4*)(g_Wlo + i) = make_uint4(l[0], l[1], l[2], l[3]);
}

extern __shared__ __align__(16) char dyn_sm[];

// ---------------------------------------------------------------------------
// Kernel 1: QKV projection, 2-term fp16 (x_f16 * (Whi + Wlo)), 2-stage pipe.
// Outputs: Q single fp16; K,V fp16 hi/lo.  All carry the 64x scale.
// ---------------------------------------------------------------------------
__global__ __launch_bounds__(128, 3) void qkv_mma_kernel()
{
    const int y    = blockIdx.y;
    const int tid  = threadIdx.x;
    const int wid  = tid >> 5;
    const int lane = tid & 31;
    const int m0g  = blockIdx.x * 64;
    const uint32_t smb = smem_to_u32(dyn_sm);

    const char* srcs[3] = {
        (const char*)g_xf,
        (const char*)(g_Whi + (size_t)y * C * H),
        (const char*)(g_Wlo + (size_t)y * C * H) };

    auto stage = [&](int t) {
        uint32_t base = smb + (t & 1) * QKV_SLOT;
        int k0 = t * 64;
#pragma unroll
        for (int i = 0; i < 12; i++) {
            int within = (i & 3) * 128 + tid;      // 0..511
            const int arr = i >> 2;                // 0=x 1=Whi 2=Wlo
            int r = within >> 3, c = within & 7;
            uint32_t dst = base + arr * TILE_BYTES + r * SKB + c * 16;
            const char* src = (arr == 0)
                ? srcs[0] + ((size_t)(m0g + r) * C + k0 + c * 8) * 2
                : srcs[arr] + ((size_t)(k0 + r) * H + c * 8) * 2;
            CP16(dst, src);
        }
        CP_COMMIT();
    };

    float o[8][4];
#pragma unroll
    for (int nt = 0; nt < 8; nt++)
#pragma unroll
        for (int e = 0; e < 4; e++) o[nt][e] = 0.0f;

    const int a_row  = wid * 16 + (lane & 7) + ((lane >> 3) & 1) * 8;
    const int a_colb = (lane >> 4) * 8;
    const int g      = lane >> 3;
    const int t_row  = (lane & 7) + (g & 1) * 8;
    const int t_colb = (g >> 1) * 8;

    const int NT = C / 64;
    stage(0);
    stage(1);

    for (int t = 0; t < NT; t++) {
        if (t + 2 <= NT) CP_WAIT1(); else CP_WAIT0();
        __syncthreads();
        uint32_t bb = smb + (t & 1) * QKV_SLOT;

        uint32_t ax[4][4];
#pragma unroll
        for (int k = 0; k < 4; k++)
            ldsm_x4(ax[k], bb + a_row * SKB + (k * 16 + a_colb) * 2);

#pragma unroll
        for (int np = 0; np < 4; np++) {
#pragma unroll
            for (int k = 0; k < 4; k++) {
                uint32_t bh[4], bl[4];
                uint32_t ad = (k * 16 + t_row) * SKB + (np * 16 + t_colb) * 2;
                ldsm_x4_t(bh, bb + TILE_BYTES     + ad);
                ldsm_x4_t(bl, bb + 2 * TILE_BYTES + ad);
                mma16816h(o[2 * np],     ax[k], bh);
                mma16816h(o[2 * np + 1], ax[k], bh + 2);
                mma16816h(o[2 * np],     ax[k], bl);
                mma16816h(o[2 * np + 1], ax[k], bl + 2);
            }
        }
        __syncthreads();
        if (t + 2 < NT) stage(t + 2);
    }

    const int r0 = m0g + wid * 16 + (lane >> 2);
    if (y == 0) {                       // Q: single fp16
#pragma unroll
        for (int nt = 0; nt < 8; nt++) {
            int c = nt * 8 + (lane & 3) * 2;
            __half2 hA = __floats2half2_rn(o[nt][0], o[nt][1]);
            __half2 hB = __floats2half2_rn(o[nt][2], o[nt][3]);
            *(uint32_t*)(g_Qf + (size_t)r0 * H + c)       = *reinterpret_cast<uint32_t*>(&hA);
            *(uint32_t*)(g_Qf + (size_t)(r0 + 8) * H + c) = *reinterpret_cast<uint32_t*>(&hB);
        }
    } else {                            // K or V: fp16 hi/lo
        __half* ohi = (y == 1) ? g_Khi : g_Vhi;
        __half* olo = (y == 1) ? g_Klo : g_Vlo;
#pragma unroll
        for (int nt = 0; nt < 8; nt++) {
            int c = nt * 8 + (lane & 3) * 2;
            uint32_t hi, lo;
            cvt_f16_hilo(o[nt][0], o[nt][1], hi, lo);
            *(uint32_t*)(ohi + (size_t)r0 * H + c) = hi;
            *(uint32_t*)(olo + (size_t)r0 * H + c) = lo;
            cvt_f16_hilo(o[nt][2], o[nt][3], hi, lo);
            *(uint32_t*)(ohi + (size_t)(r0 + 8) * H + c) = hi;
            *(uint32_t*)(olo + (size_t)(r0 + 8) * H + c) = lo;
        }
    }
}

// ---------------------------------------------------------------------------
// Kernel 2: flash attention, no-max softmax, 2-stage double-buffered K+V
// (R8 schedule), Q fragments in registers (fp16 single, from global).
// grid = (T/64, NCHUNK, BATCH), block = 128 (4 warps x 16 queries), 3 CTAs/SM.
// ---------------------------------------------------------------------------
__global__ __launch_bounds__(128, 3) void flash_mma_kernel()
{
    const int b     = blockIdx.z;
    const int chunk = blockIdx.y;
    const int qt    = blockIdx.x;
    const int tid   = threadIdx.x;
    const int wid   = tid >> 5;
    const int lane  = tid & 31;
    const int q0    = qt * 64;

    const int seg_begin = chunk * CHUNK_KEYS;
    const int seg_end   = min(seg_begin + CHUNK_KEYS, q0 + 64);

    if (seg_begin >= seg_end) {            // chunk beyond causal range
        for (int r = tid; r < 64; r += 128) {
            g_l[((size_t)(b * T) + q0 + r) * NCHUNK + chunk] = 0.0f;
        }
        return;
    }

    const uint32_t smb = smem_to_u32(dyn_sm);
    const int NT = (seg_end - seg_begin + 63) / 64;  // 1..8

    const char* kvsrc[4] = {
        (const char*)g_Khi, (const char*)g_Klo,
        (const char*)g_Vhi, (const char*)g_Vlo };

    // stage tile t (K hi/lo + V hi/lo) into slot t&1
    auto stage = [&](int t) {
        uint32_t base = smb + (t & 1) * KV_SLOT;
        int kt = seg_begin + t * 64;
#pragma unroll
        for (int i = 0; i < 16; i++) {
            int within = (i & 3) * 128 + tid;        // 0..511
            const int arr = i >> 2;                  // Khi Klo Vhi Vlo
            int r = within >> 3, c = within & 7;
            uint32_t dst = base + arr * TILE_BYTES + r * SKB + c * 16;
            const char* src = kvsrc[arr] + ((size_t)(b * T + kt + r) * H + c * 8) * 2;
            CP16(dst, src);
        }
        CP_COMMIT();
    };

    // ---- Q fragments from global (canonical m16n8k16 A layout, fp16) ----
    uint32_t qf[4][4];
    {
        const int rl = wid * 16 + (lane >> 2);
        const int tg = lane & 3;
        const uint32_t* Q32 = (const uint32_t*)(g_Qf + (size_t)(b * T + q0) * H);
#pragma unroll
        for (int k = 0; k < 4; k++) {
            int cb = k * 8 + tg;                     // uint32 col of 32/row
            qf[k][0] = Q32[(size_t)rl * 32 + cb];
            qf[k][1] = Q32[(size_t)(rl + 8) * 32 + cb];
            qf[k][2] = Q32[(size_t)rl * 32 + cb + 4];
            qf[k][3] = Q32[(size_t)(rl + 8) * 32 + cb + 4];
        }
    }

    stage(0);
    if (NT > 1) stage(1);

    const int g      = lane >> 3;
    const int nt_row = (lane & 7) + (g >> 1) * 8;   // K non-trans B-frag
    const int nt_colb = (g & 1) * 8;
    const int t_row  = (lane & 7) + (g & 1) * 8;    // V trans B-frag
    const int t_colb = (g >> 1) * 8;

    float o[8][4];
#pragma unroll
    for (int nt = 0; nt < 8; nt++)
#pragma unroll
        for (int e = 0; e < 4; e++) o[nt][e] = 0.0f;
    float l0 = 0.0f, l1 = 0.0f;

    const int row_i0 = (wid << 4) + (lane >> 2);

    for (int t = 0; t < NT; t++) {
        if (t + 2 <= NT) CP_WAIT1(); else CP_WAIT0();
        __syncthreads();
        const uint32_t kb = smb + (t & 1) * KV_SLOT;
        const uint32_t vb = kb + 2 * TILE_BYTES;
        const int kt = seg_begin + t * 64;

        // ---- S = Q (Khi + Klo)  (2-term fp16) ----
        float s[8][4];
#pragma unroll
        for (int nt = 0; nt < 8; nt++)
#pragma unroll
            for (int e = 0; e < 4; e++) s[nt][e] = 0.0f;

#pragma unroll
        for (int k = 0; k < 4; k++) {
#pragma unroll
            for (int np = 0; np < 4; np++) {
                uint32_t bh[4], bl[4];
                uint32_t ad = (np * 16 + nt_row) * SKB + (k * 16 + nt_colb) * 2;
                ldsm_x4(bh, kb + ad);
                ldsm_x4(bl, kb + TILE_BYTES + ad);
                mma16816h(s[2 * np],     qf[k], bh);
                mma16816h(s[2 * np + 1], qf[k], bh + 2);
                mma16816h(s[2 * np],     qf[k], bl);
                mma16816h(s[2 * np + 1], qf[k], bl + 2);
            }
        }

        // ---- softmax numerator: p = exp2(v), no max-subtraction needed ----
        const bool needmask = (kt + 63 > q0 + (wid << 4));
        float ls0 = 0.0f, ls1 = 0.0f;
#pragma unroll
        for (int nt = 0; nt < 8; nt++) {
#pragma unroll
            for (int e = 0; e < 4; e++) {
                float v = s[nt][e] * SC2;
                if (needmask) {
                    int j = kt + nt * 8 + (lane & 3) * 2 + (e & 1);
                    int i = q0 + row_i0 + (e >> 1) * 8;
                    if (j > i) v = -INFINITY;   // exp2 -> 0
                }
                s[nt][e] = exp2f(v);
            }
            ls0 += s[nt][0] + s[nt][1];
            ls1 += s[nt][2] + s[nt][3];
        }
        l0 += ls0;
        l1 += ls1;

        // ---- O += P (Vhi + Vlo)  (2-term fp16) ----
#pragma unroll
        for (int k = 0; k < 4; k++) {
            uint32_t aP[4];
#pragma unroll
            for (int h = 0; h < 2; h++) {
                int nt = 2 * k + h;
                __half2 pA = __floats2half2_rn(s[nt][0], s[nt][1]);
                __half2 pB = __floats2half2_rn(s[nt][2], s[nt][3]);
                aP[h * 2 + 0] = *reinterpret_cast<uint32_t*>(&pA);
                aP[h * 2 + 1] = *reinterpret_cast<uint32_t*>(&pB);
            }
#pragma unroll
            for (int dp = 0; dp < 4; dp++) {
                uint32_t bh[4], bl[4];
                uint32_t ad = (k * 16 + t_row) * SKB + (dp * 16 + t_colb) * 2;
                ldsm_x4_t(bh, vb + ad);
                ldsm_x4_t(bl, vb + TILE_BYTES + ad);
                mma16816h(o[2 * dp],     aP, bh);
                mma16816h(o[2 * dp + 1], aP, bh + 2);
                mma16816h(o[2 * dp],     aP, bl);
                mma16816h(o[2 * dp + 1], aP, bl + 2);
            }
        }

        __syncthreads();                  // all reads of slot (t&1) done
        if (t + 2 < NT) stage(t + 2);     // refill freed slot
    }

    // per-row quad sum of l
    l0 += __shfl_xor_sync(0xFFFFFFFFu, l0, 1);
    l0 += __shfl_xor_sync(0xFFFFFFFFu, l0, 2);
    l1 += __shfl_xor_sync(0xFFFFFFFFu, l1, 1);
    l1 += __shfl_xor_sync(0xFFFFFFFFu, l1, 2);

    // ---- write chunk partials (o carries the 64x V scale) ----
    const int r0g = q0 + row_i0;
    const size_t pb0 = ((size_t)(b * T) + r0g) * NCHUNK + chunk;
    const size_t pb1 = ((size_t)(b * T) + r0g + 8) * NCHUNK + chunk;
#pragma unroll
    for (int nt = 0; nt < 8; nt++) {
        int c = nt * 8 + (lane & 3) * 2;
        *(float2*)&g_acc[pb0 * H + c] = make_float2(o[nt][0], o[nt][1]);
        *(float2*)&g_acc[pb1 * H + c] = make_float2(o[nt][2], o[nt][3]);
    }
    if ((lane & 3) == 0) {
        g_l[pb0] = l0;
        g_l[pb1] = l1;
    }
}

// ---------------------------------------------------------------------------
// Kernel 3: combine chunk partials: plain sums (weights are all 1).
// Skip l==0 chunks (covers never-launched chunks whose acc is garbage).
// ---------------------------------------------------------------------------
__global__ __launch_bounds__(256) void combine_kernel(float* __restrict__ out)
{
    int idx   = blockIdx.x * 256 + threadIdx.x;
    int d     = idx & (H - 1);
    int query = idx >> 6;

    float L = 0.0f, o = 0.0f;
#pragma unroll
    for (int i = 0; i < NCHUNK; i++) {
        float li = g_l[(size_t)query * NCHUNK + i];
        if (li > 0.0f) {
            L += li;
            o += g_acc[((size_t)query * NCHUNK + i) * H + d];
        }
    }
    out[idx] = o * INV_VSCALE / L;
}

// ---------------------------------------------------------------------------
extern "C" void kernel_launch(void* const* d_in, const int* in_sizes, int n_in,
                              void* d_out, int out_size)
{
    const float* x  = (const float*)d_in[0];
    const float* Wq = (const float*)d_in[1];
    const float* Wk = (const float*)d_in[2];
    const float* Wv = (const float*)d_in[3];
    float* out = (float*)d_out;

    // host-side, idempotent, capture-safe
    cudaFuncSetAttribute(qkv_mma_kernel,
        cudaFuncAttributeMaxDynamicSharedMemorySize, QKV_SMEM);
    cudaFuncSetAttribute(flash_mma_kernel,
        cudaFuncAttributeMaxDynamicSharedMemorySize, FLASH_SMEM);

    prep_x_kernel<<<(size_t)M_TOT * C / 2048, 256>>>(x);
    prep_w_kernel<<<3 * C * H / 2048, 256>>>(Wq, Wk, Wv);
    qkv_mma_kernel<<<dim3(M_TOT / 64, 3), 128, QKV_SMEM>>>();
    flash_mma_kernel<<<dim3(T / 64, NCHUNK, BATCH), 128, FLASH_SMEM>>>();
    combine_kernel<<<(M_TOT * H) / 256, 256>>>(out);
}

// round 15
// speedup vs baseline: 1.1101x; 1.1101x over previous
#include <cuda_runtime.h>
#include <cuda_bf16.h>
#include <cuda_fp16.h>
#include <math.h>
#include <stdint.h>

#define BATCH 4
#define T 4096
#define C 768
#define H 64
#define M_TOT (BATCH * T)

// work-balanced split-K: fixed 512-key chunks, up to 8 per query tile
#define NCHUNK 8
#define CHUNK_KEYS 512

// W (and hence q,k,v) are pre-scaled by 64.  Scores: s' = q'·k' = 4096·q·k.
// softmax exponent = s' · SC2;  |exponent| <~ 1, so no max-subtraction.
#define SC2 4.40275588e-5f        // 0.125 * log2(e) / 4096
#define INV_VSCALE 0.015625f      // 1/64 (undo V scaling in combine)

// ---- pre-converted operand arrays (fp16 throughout the fast path) ----
__device__ __align__(16) __half g_xf[(size_t)M_TOT * C];      // x, single fp16
__device__ __align__(16) __half g_Whi[3 * C * H];             // 64*W hi
__device__ __align__(16) __half g_Wlo[3 * C * H];             // 64*W lo
__device__ __align__(16) __half g_Qf [M_TOT * H];             // q' single fp16
__device__ __align__(16) __half g_Kf [M_TOT * H];             // k' single fp16
__device__ __align__(16) __half g_Vhi[M_TOT * H];             // v' hi
__device__ __align__(16) __half g_Vlo[M_TOT * H];             // v' lo
__device__ float g_l[(size_t)M_TOT * NCHUNK];
__device__ float g_acc[(size_t)M_TOT * NCHUNK * H];

// ============================================================================
// Primitives
// ============================================================================
__device__ __forceinline__ uint32_t smem_to_u32(const void* smem_ptr) {
    uint32_t addr;
    asm("{ .reg .u64 tmp; cvta.to.shared.u64 tmp, %1; cvt.u32.u64 %0, tmp; }"
        : "=r"(addr) : "l"(smem_ptr));
    return addr;
}

// fp16 MMA: D(16x8,f32) += A(16x16,f16) * B(16x8,f16)
__device__ __forceinline__ void mma16816h(float* d, const uint32_t* a, const uint32_t* b) {
    asm volatile(
        "mma.sync.aligned.m16n8k16.row.col.f32.f16.f16.f32 "
        "{%0,%1,%2,%3}, {%4,%5,%6,%7}, {%8,%9}, {%0,%1,%2,%3};"
        : "+f"(d[0]), "+f"(d[1]), "+f"(d[2]), "+f"(d[3])
        : "r"(a[0]), "r"(a[1]), "r"(a[2]), "r"(a[3]), "r"(b[0]), "r"(b[1]));
}

__device__ __forceinline__ void ldsm_x4(uint32_t* r, uint32_t a) {
    asm volatile("ldmatrix.sync.aligned.m8n8.x4.shared.b16 {%0,%1,%2,%3}, [%4];"
        : "=r"(r[0]), "=r"(r[1]), "=r"(r[2]), "=r"(r[3]) : "r"(a));
}

__device__ __forceinline__ void ldsm_x4_t(uint32_t* r, uint32_t a) {
    asm volatile("ldmatrix.sync.aligned.m8n8.x4.trans.shared.b16 {%0,%1,%2,%3}, [%4];"
        : "=r"(r[0]), "=r"(r[1]), "=r"(r[2]), "=r"(r[3]) : "r"(a));
}

#define CP16(dst, src) \
    asm volatile("cp.async.cg.shared.global [%0], [%1], 16;" \
                 :: "r"(dst), "l"(src) : "memory")
#define CP_COMMIT() asm volatile("cp.async.commit_group;" ::: "memory")
#define CP_WAIT0()  asm volatile("cp.async.wait_group 0;" ::: "memory")
#define CP_WAIT1()  asm volatile("cp.async.wait_group 1;" ::: "memory")

__device__ __forceinline__ void cvt_f16_hilo(float vx, float vy, uint32_t& hi, uint32_t& lo) {
    __half2 h = __floats2half2_rn(vx, vy);
    hi = *reinterpret_cast<uint32_t*>(&h);
    float rx = vx - __half2float(__low2half(h));
    float ry = vy - __half2float(__high2half(h));
    __half2 l2 = __floats2half2_rn(rx, ry);
    lo = *reinterpret_cast<uint32_t*>(&l2);
}

// SMEM tile: 64 rows x 64 f16 in 144B-stride rows (conflict-free ldmatrix)
#define SKB 144
#define TILE_BYTES (64 * SKB)             // 9216
#define QKV_SLOT (3 * TILE_BYTES)         // xf16 | Whi | Wlo = 27648
#define QKV_SMEM (2 * QKV_SLOT)           // 55296 (2-stage)
#define KV_SLOT (3 * TILE_BYTES)          // Kf | Vhi | Vlo = 27648
#define FLASH_SMEM (2 * KV_SLOT)          // 55296 (2-stage; 4 CTAs/SM)

// ---------------------------------------------------------------------------
// Prep kernels
// ---------------------------------------------------------------------------
__global__ __launch_bounds__(256) void prep_x_kernel(const float* __restrict__ x)
{
    size_t i = ((size_t)blockIdx.x * 256 + threadIdx.x) * 8;
    float4 a = *(const float4*)(x + i);
    float4 b = *(const float4*)(x + i + 4);
    __half2 h0 = __floats2half2_rn(a.x, a.y);
    __half2 h1 = __floats2half2_rn(a.z, a.w);
    __half2 h2 = __floats2half2_rn(b.x, b.y);
    __half2 h3 = __floats2half2_rn(b.z, b.w);
    *(uint4*)(g_xf + i) = make_uint4(
        *reinterpret_cast<uint32_t*>(&h0), *reinterpret_cast<uint32_t*>(&h1),
        *reinterpret_cast<uint32_t*>(&h2), *reinterpret_cast<uint32_t*>(&h3));
}

__global__ __launch_bounds__(256) void prep_w_kernel(
    const float* __restrict__ Wq, const float* __restrict__ Wk,
    const float* __restrict__ Wv)
{
    size_t i = ((size_t)blockIdx.x * 256 + threadIdx.x) * 8;
    int which = (int)(i / (C * H));
    const float* W = (which == 0) ? Wq : (which == 1) ? Wk : Wv;
    size_t local = i - (size_t)which * (C * H);
    float4 a = *(const float4*)(W + local);
    float4 b = *(const float4*)(W + local + 4);
    // scale by 64 (exact) so the f16 residual (lo) stays in normal range
    uint32_t h[4], l[4];
    cvt_f16_hilo(a.x * 64.0f, a.y * 64.0f, h[0], l[0]);
    cvt_f16_hilo(a.z * 64.0f, a.w * 64.0f, h[1], l[1]);
    cvt_f16_hilo(b.x * 64.0f, b.y * 64.0f, h[2], l[2]);
    cvt_f16_hilo(b.z * 64.0f, b.w * 64.0f, h[3], l[3]);
    *(uint4*)(g_Whi + i) = make_uint4(h[0], h[1], h[2], h[3]);
    *(uint4*)(g_Wlo + i) = make_uint4(l[0], l[1], l[2], l[3]);
}

extern __shared__ __align__(16) char dyn_sm[];

// ---------------------------------------------------------------------------
// Kernel 1: QKV projection, 2-term fp16 (x_f16 * (Whi + Wlo)), 2-stage pipe.
// Outputs: Q,K single fp16; V fp16 hi/lo.  All carry the 64x scale.
// ---------------------------------------------------------------------------
__global__ __launch_bounds__(128, 3) void qkv_mma_kernel()
{
    const int y    = blockIdx.y;
    const int tid  = threadIdx.x;
    const int wid  = tid >> 5;
    const int lane = tid & 31;
    const int m0g  = blockIdx.x * 64;
    const uint32_t smb = smem_to_u32(dyn_sm);

    const char* srcs[3] = {
        (const char*)g_xf,
        (const char*)(g_Whi + (size_t)y * C * H),
        (const char*)(g_Wlo + (size_t)y * C * H) };

    auto stage = [&](int t) {
        uint32_t base = smb + (t & 1) * QKV_SLOT;
        int k0 = t * 64;
#pragma unroll
        for (int i = 0; i < 12; i++) {
            int within = (i & 3) * 128 + tid;      // 0..511
            const int arr = i >> 2;                // 0=x 1=Whi 2=Wlo
            int r = within >> 3, c = within & 7;
            uint32_t dst = base + arr * TILE_BYTES + r * SKB + c * 16;
            const char* src = (arr == 0)
                ? srcs[0] + ((size_t)(m0g + r) * C + k0 + c * 8) * 2
                : srcs[arr] + ((size_t)(k0 + r) * H + c * 8) * 2;
            CP16(dst, src);
        }
        CP_COMMIT();
    };

    float o[8][4];
#pragma unroll
    for (int nt = 0; nt < 8; nt++)
#pragma unroll
        for (int e = 0; e < 4; e++) o[nt][e] = 0.0f;

    const int a_row  = wid * 16 + (lane & 7) + ((lane >> 3) & 1) * 8;
    const int a_colb = (lane >> 4) * 8;
    const int g      = lane >> 3;
    const int t_row  = (lane & 7) + (g & 1) * 8;
    const int t_colb = (g >> 1) * 8;

    const int NT = C / 64;
    stage(0);
    stage(1);

    for (int t = 0; t < NT; t++) {
        if (t + 2 <= NT) CP_WAIT1(); else CP_WAIT0();
        __syncthreads();
        uint32_t bb = smb + (t & 1) * QKV_SLOT;

        uint32_t ax[4][4];
#pragma unroll
        for (int k = 0; k < 4; k++)
            ldsm_x4(ax[k], bb + a_row * SKB + (k * 16 + a_colb) * 2);

#pragma unroll
        for (int np = 0; np < 4; np++) {
#pragma unroll
            for (int k = 0; k < 4; k++) {
                uint32_t bh[4], bl[4];
                uint32_t ad = (k * 16 + t_row) * SKB + (np * 16 + t_colb) * 2;
                ldsm_x4_t(bh, bb + TILE_BYTES     + ad);
                ldsm_x4_t(bl, bb + 2 * TILE_BYTES + ad);
                mma16816h(o[2 * np],     ax[k], bh);
                mma16816h(o[2 * np + 1], ax[k], bh + 2);
                mma16816h(o[2 * np],     ax[k], bl);
                mma16816h(o[2 * np + 1], ax[k], bl + 2);
            }
        }
        __syncthreads();
        if (t + 2 < NT) stage(t + 2);
    }

    const int r0 = m0g + wid * 16 + (lane >> 2);
    if (y < 2) {                        // Q or K: single fp16
        __half* of = (y == 0) ? g_Qf : g_Kf;
#pragma unroll
        for (int nt = 0; nt < 8; nt++) {
            int c = nt * 8 + (lane & 3) * 2;
            __half2 hA = __floats2half2_rn(o[nt][0], o[nt][1]);
            __half2 hB = __floats2half2_rn(o[nt][2], o[nt][3]);
            *(uint32_t*)(of + (size_t)r0 * H + c)       = *reinterpret_cast<uint32_t*>(&hA);
            *(uint32_t*)(of + (size_t)(r0 + 8) * H + c) = *reinterpret_cast<uint32_t*>(&hB);
        }
    } else {                            // V: fp16 hi/lo
#pragma unroll
        for (int nt = 0; nt < 8; nt++) {
            int c = nt * 8 + (lane & 3) * 2;
            uint32_t hi, lo;
            cvt_f16_hilo(o[nt][0], o[nt][1], hi, lo);
            *(uint32_t*)(g_Vhi + (size_t)r0 * H + c) = hi;
            *(uint32_t*)(g_Vlo + (size_t)r0 * H + c) = lo;
            cvt_f16_hilo(o[nt][2], o[nt][3], hi, lo);
            *(uint32_t*)(g_Vhi + (size_t)(r0 + 8) * H + c) = hi;
            *(uint32_t*)(g_Vlo + (size_t)(r0 + 8) * H + c) = lo;
        }
    }
}

// ---------------------------------------------------------------------------
// Kernel 2: flash attention.  S = Qf16 * Kf16 (1-term), PV = Pf16*(Vhi+Vlo).
// 2-stage double-buffered [K|Vhi|Vlo] slots, Q frags in registers, 4 CTAs/SM.
// grid = (T/64, NCHUNK, BATCH), block = 128 (4 warps x 16 queries).
// ---------------------------------------------------------------------------
__global__ __launch_bounds__(128, 4) void flash_mma_kernel()
{
    const int b     = blockIdx.z;
    const int chunk = blockIdx.y;
    const int qt    = blockIdx.x;
    const int tid   = threadIdx.x;
    const int wid   = tid >> 5;
    const int lane  = tid & 31;
    const int q0    = qt * 64;

    const int seg_begin = chunk * CHUNK_KEYS;
    const int seg_end   = min(seg_begin + CHUNK_KEYS, q0 + 64);

    if (seg_begin >= seg_end) {            // chunk beyond causal range
        for (int r = tid; r < 64; r += 128) {
            g_l[((size_t)(b * T) + q0 + r) * NCHUNK + chunk] = 0.0f;
        }
        return;
    }

    const uint32_t smb = smem_to_u32(dyn_sm);
    const int NT = (seg_end - seg_begin + 63) / 64;  // 1..8

    const char* kvsrc[3] = {
        (const char*)g_Kf, (const char*)g_Vhi, (const char*)g_Vlo };

    // stage tile t (K + V hi/lo) into slot t&1
    auto stage = [&](int t) {
        uint32_t base = smb + (t & 1) * KV_SLOT;
        int kt = seg_begin + t * 64;
#pragma unroll
        for (int i = 0; i < 12; i++) {
            int within = (i & 3) * 128 + tid;        // 0..511
            const int arr = i >> 2;                  // 0=K 1=Vhi 2=Vlo
            int r = within >> 3, c = within & 7;
            uint32_t dst = base + arr * TILE_BYTES + r * SKB + c * 16;
            const char* src = kvsrc[arr] + ((size_t)(b * T + kt + r) * H + c * 8) * 2;
            CP16(dst, src);
        }
        CP_COMMIT();
    };

    // ---- Q fragments from global (canonical m16n8k16 A layout, fp16) ----
    uint32_t qf[4][4];
    {
        const int rl = wid * 16 + (lane >> 2);
        const int tg = lane & 3;
        const uint32_t* Q32 = (const uint32_t*)(g_Qf + (size_t)(b * T + q0) * H);
#pragma unroll
        for (int k = 0; k < 4; k++) {
            int cb = k * 8 + tg;                     // uint32 col of 32/row
            qf[k][0] = Q32[(size_t)rl * 32 + cb];
            qf[k][1] = Q32[(size_t)(rl + 8) * 32 + cb];
            qf[k][2] = Q32[(size_t)rl * 32 + cb + 4];
            qf[k][3] = Q32[(size_t)(rl + 8) * 32 + cb + 4];
        }
    }

    stage(0);
    if (NT > 1) stage(1);

    const int g      = lane >> 3;
    const int nt_row = (lane & 7) + (g >> 1) * 8;   // K non-trans B-frag
    const int nt_colb = (g & 1) * 8;
    const int t_row  = (lane & 7) + (g & 1) * 8;    // V trans B-frag
    const int t_colb = (g >> 1) * 8;

    float o[8][4];
#pragma unroll
    for (int nt = 0; nt < 8; nt++)
#pragma unroll
        for (int e = 0; e < 4; e++) o[nt][e] = 0.0f;
    float l0 = 0.0f, l1 = 0.0f;

    const int row_i0 = (wid << 4) + (lane >> 2);

    for (int t = 0; t < NT; t++) {
        if (t + 2 <= NT) CP_WAIT1(); else CP_WAIT0();
        __syncthreads();
        const uint32_t kb = smb + (t & 1) * KV_SLOT;
        const uint32_t vb = kb + TILE_BYTES;
        const int kt = seg_begin + t * 64;

        // ---- S = Q K (single-term fp16) ----
        float s[8][4];
#pragma unroll
        for (int nt = 0; nt < 8; nt++)
#pragma unroll
            for (int e = 0; e < 4; e++) s[nt][e] = 0.0f;

#pragma unroll
        for (int k = 0; k < 4; k++) {
#pragma unroll
            for (int np = 0; np < 4; np++) {
                uint32_t bk[4];
                uint32_t ad = (np * 16 + nt_row) * SKB + (k * 16 + nt_colb) * 2;
                ldsm_x4(bk, kb + ad);
                mma16816h(s[2 * np],     qf[k], bk);
                mma16816h(s[2 * np + 1], qf[k], bk + 2);
            }
        }

        // ---- softmax numerator: p = exp2(v), no max-subtraction needed ----
        const bool needmask = (kt + 63 > q0 + (wid << 4));
        float ls0 = 0.0f, ls1 = 0.0f;
#pragma unroll
        for (int nt = 0; nt < 8; nt++) {
#pragma unroll
            for (int e = 0; e < 4; e++) {
                float v = s[nt][e] * SC2;
                if (needmask) {
                    int j = kt + nt * 8 + (lane & 3) * 2 + (e & 1);
                    int i = q0 + row_i0 + (e >> 1) * 8;
                    if (j > i) v = -INFINITY;   // exp2 -> 0
                }
                s[nt][e] = exp2f(v);
            }
            ls0 += s[nt][0] + s[nt][1];
            ls1 += s[nt][2] + s[nt][3];
        }
        l0 += ls0;
        l1 += ls1;

        // ---- O += P (Vhi + Vlo)  (2-term fp16) ----
#pragma unroll
        for (int k = 0; k < 4; k++) {
            uint32_t aP[4];
#pragma unroll
            for (int h = 0; h < 2; h++) {
                int nt = 2 * k + h;
                __half2 pA = __floats2half2_rn(s[nt][0], s[nt][1]);
                __half2 pB = __floats2half2_rn(s[nt][2], s[nt][3]);
                aP[h * 2 + 0] = *reinterpret_cast<uint32_t*>(&pA);
                aP[h * 2 + 1] = *reinterpret_cast<uint32_t*>(&pB);
            }
#pragma unroll
            for (int dp = 0; dp < 4; dp++) {
                uint32_t bh[4], bl[4];
                uint32_t ad = (k * 16 + t_row) * SKB + (dp * 16 + t_colb) * 2;
                ldsm_x4_t(bh, vb + ad);
                ldsm_x4_t(bl, vb + TILE_BYTES + ad);
                mma16816h(o[2 * dp],     aP, bh);
                mma16816h(o[2 * dp + 1], aP, bh + 2);
                mma16816h(o[2 * dp],     aP, bl);
                mma16816h(o[2 * dp + 1], aP, bl + 2);
            }
        }

        __syncthreads();                  // all reads of slot (t&1) done
        if (t + 2 < NT) stage(t + 2);     // refill freed slot
    }

    // per-row quad sum of l
    l0 += __shfl_xor_sync(0xFFFFFFFFu, l0, 1);
    l0 += __shfl_xor_sync(0xFFFFFFFFu, l0, 2);
    l1 += __shfl_xor_sync(0xFFFFFFFFu, l1, 1);
    l1 += __shfl_xor_sync(0xFFFFFFFFu, l1, 2);

    // ---- write chunk partials (o carries the 64x V scale) ----
    const int r0g = q0 + row_i0;
    const size_t pb0 = ((size_t)(b * T) + r0g) * NCHUNK + chunk;
    const size_t pb1 = ((size_t)(b * T) + r0g + 8) * NCHUNK + chunk;
#pragma unroll
    for (int nt = 0; nt < 8; nt++) {
        int c = nt * 8 + (lane & 3) * 2;
        *(float2*)&g_acc[pb0 * H + c] = make_float2(o[nt][0], o[nt][1]);
        *(float2*)&g_acc[pb1 * H + c] = make_float2(o[nt][2], o[nt][3]);
    }
    if ((lane & 3) == 0) {
        g_l[pb0] = l0;
        g_l[pb1] = l1;
    }
}

// ---------------------------------------------------------------------------
// Kernel 3: combine chunk partials: plain sums (weights are all 1).
// Skip l==0 chunks (covers never-launched chunks whose acc is garbage).
// ---------------------------------------------------------------------------
__global__ __launch_bounds__(256) void combine_kernel(float* __restrict__ out)
{
    int idx   = blockIdx.x * 256 + threadIdx.x;
    int d     = idx & (H - 1);
    int query = idx >> 6;

    float L = 0.0f, o = 0.0f;
#pragma unroll
    for (int i = 0; i < NCHUNK; i++) {
        float li = g_l[(size_t)query * NCHUNK + i];
        if (li > 0.0f) {
            L += li;
            o += g_acc[((size_t)query * NCHUNK + i) * H + d];
        }
    }
    out[idx] = o * INV_VSCALE / L;
}

// ---------------------------------------------------------------------------
extern "C" void kernel_launch(void* const* d_in, const int* in_sizes, int n_in,
                              void* d_out, int out_size)
{
    const float* x  = (const float*)d_in[0];
    const float* Wq = (const float*)d_in[1];
    const float* Wk = (const float*)d_in[2];
    const float* Wv = (const float*)d_in[3];
    float* out = (float*)d_out;

    // host-side, idempotent, capture-safe
    cudaFuncSetAttribute(qkv_mma_kernel,
        cudaFuncAttributeMaxDynamicSharedMemorySize, QKV_SMEM);
    cudaFuncSetAttribute(flash_mma_kernel,
        cudaFuncAttributeMaxDynamicSharedMemorySize, FLASH_SMEM);

    prep_x_kernel<<<(size_t)M_TOT * C / 2048, 256>>>(x);
    prep_w_kernel<<<3 * C * H / 2048, 256>>>(Wq, Wk, Wv);
    qkv_mma_kernel<<<dim3(M_TOT / 64, 3), 128, QKV_SMEM>>>();
    flash_mma_kernel<<<dim3(T / 64, NCHUNK, BATCH), 128, FLASH_SMEM>>>();
    combine_kernel<<<(M_TOT * H) / 256, 256>>>(out);
}

// round 17
// speedup vs baseline: 1.2296x; 1.1077x over previous
#include <cuda_runtime.h>
#include <cuda_bf16.h>
#include <cuda_fp16.h>
#include <math.h>
#include <stdint.h>

#define BATCH 4
#define T 4096
#define C 768
#define H 64
#define M_TOT (BATCH * T)

// work-balanced split-K: fixed 512-key chunks, up to 8 per query tile
#define NCHUNK 8
#define CHUNK_KEYS 512

// W (and hence q,k,v) are pre-scaled by 64.  Scores: s' = q'·k' = 4096·q·k.
// softmax exponent = s' · SC2;  |exponent| <~ 1, so no max-subtraction.
#define SC2 4.40275588e-5f        // 0.125 * log2(e) / 4096
#define INV_VSCALE 0.015625f      // 1/64 (undo V scaling in combine)

// ---- pre-converted operand arrays (fp16 throughout the fast path) ----
__device__ __align__(16) __half g_xf[(size_t)M_TOT * C];      // x, single fp16
__device__ __align__(16) __half g_Wf [3 * C * H];             // 64*W single fp16
__device__ __align__(16) __half g_Qf [M_TOT * H];             // q' single fp16
__device__ __align__(16) __half g_Kf [M_TOT * H];             // k' single fp16
__device__ __align__(16) __half g_Vhi[M_TOT * H];             // v' hi
__device__ __align__(16) __half g_Vlo[M_TOT * H];             // v' lo
__device__ float g_l[(size_t)M_TOT * NCHUNK];
__device__ __align__(16) float g_acc[(size_t)M_TOT * NCHUNK * H];  // fp32 partials

// ============================================================================
// Primitives
// ============================================================================
__device__ __forceinline__ uint32_t smem_to_u32(const void* smem_ptr) {
    uint32_t addr;
    asm("{ .reg .u64 tmp; cvta.to.shared.u64 tmp, %1; cvt.u32.u64 %0, tmp; }"
        : "=r"(addr) : "l"(smem_ptr));
    return addr;
}

// fp16 MMA: D(16x8,f32) += A(16x16,f16) * B(16x8,f16)
__device__ __forceinline__ void mma16816h(float* d, const uint32_t* a, const uint32_t* b) {
    asm volatile(
        "mma.sync.aligned.m16n8k16.row.col.f32.f16.f16.f32 "
        "{%0,%1,%2,%3}, {%4,%5,%6,%7}, {%8,%9}, {%0,%1,%2,%3};"
        : "+f"(d[0]), "+f"(d[1]), "+f"(d[2]), "+f"(d[3])
        : "r"(a[0]), "r"(a[1]), "r"(a[2]), "r"(a[3]), "r"(b[0]), "r"(b[1]));
}

__device__ __forceinline__ void ldsm_x4(uint32_t* r, uint32_t a) {
    asm volatile("ldmatrix.sync.aligned.m8n8.x4.shared.b16 {%0,%1,%2,%3}, [%4];"
        : "=r"(r[0]), "=r"(r[1]), "=r"(r[2]), "=r"(r[3]) : "r"(a));
}

__device__ __forceinline__ void ldsm_x4_t(uint32_t* r, uint32_t a) {
    asm volatile("ldmatrix.sync.aligned.m8n8.x4.trans.shared.b16 {%0,%1,%2,%3}, [%4];"
        : "=r"(r[0]), "=r"(r[1]), "=r"(r[2]), "=r"(r[3]) : "r"(a));
}

#define CP16(dst, src) \
    asm volatile("cp.async.cg.shared.global [%0], [%1], 16;" \
                 :: "r"(dst), "l"(src) : "memory")
#define CP_COMMIT() asm volatile("cp.async.commit_group;" ::: "memory")
#define CP_WAIT0()  asm volatile("cp.async.wait_group 0;" ::: "memory")
#define CP_WAIT1()  asm volatile("cp.async.wait_group 1;" ::: "memory")

__device__ __forceinline__ void cvt_f16_hilo(float vx, float vy, uint32_t& hi, uint32_t& lo) {
    __half2 h = __floats2half2_rn(vx, vy);
    hi = *reinterpret_cast<uint32_t*>(&h);
    float rx = vx - __half2float(__low2half(h));
    float ry = vy - __half2float(__high2half(h));
    __half2 l2 = __floats2half2_rn(rx, ry);
    lo = *reinterpret_cast<uint32_t*>(&l2);
}

// SMEM tile: 64 rows x 64 f16 in 144B-stride rows (conflict-free ldmatrix)
#define SKB 144
#define TILE_BYTES (64 * SKB)             // 9216
#define QKV_SLOT (2 * TILE_BYTES)         // xf16 | Wf = 18432
#define QKV_SMEM (2 * QKV_SLOT)           // 36864 (2-stage)
#define KV_SLOT (3 * TILE_BYTES)          // Kf | Vhi | Vlo = 27648
#define FLASH_SMEM (2 * KV_SLOT)          // 55296 (2-stage; 4 CTAs/SM)

// ---------------------------------------------------------------------------
// Prep kernels
// ---------------------------------------------------------------------------
__global__ __launch_bounds__(256) void prep_x_kernel(const float* __restrict__ x)
{
    size_t i = ((size_t)blockIdx.x * 256 + threadIdx.x) * 8;
    float4 a = *(const float4*)(x + i);
    float4 b = *(const float4*)(x + i + 4);
    __half2 h0 = __floats2half2_rn(a.x, a.y);
    __half2 h1 = __floats2half2_rn(a.z, a.w);
    __half2 h2 = __floats2half2_rn(b.x, b.y);
    __half2 h3 = __floats2half2_rn(b.z, b.w);
    *(uint4*)(g_xf + i) = make_uint4(
        *reinterpret_cast<uint32_t*>(&h0), *reinterpret_cast<uint32_t*>(&h1),
        *reinterpret_cast<uint32_t*>(&h2), *reinterpret_cast<uint32_t*>(&h3));
}

__global__ __launch_bounds__(256) void prep_w_kernel(
    const float* __restrict__ Wq, const float* __restrict__ Wk,
    const float* __restrict__ Wv)
{
    size_t i = ((size_t)blockIdx.x * 256 + threadIdx.x) * 8;
    int which = (int)(i / (C * H));
    const float* W = (which == 0) ? Wq : (which == 1) ? Wk : Wv;
    size_t local = i - (size_t)which * (C * H);
    float4 a = *(const float4*)(W + local);
    float4 b = *(const float4*)(W + local + 4);
    // scale by 64 (exact): keeps values well inside fp16 normal range
    __half2 h0 = __floats2half2_rn(a.x * 64.0f, a.y * 64.0f);
    __half2 h1 = __floats2half2_rn(a.z * 64.0f, a.w * 64.0f);
    __half2 h2 = __floats2half2_rn(b.x * 64.0f, b.y * 64.0f);
    __half2 h3 = __floats2half2_rn(b.z * 64.0f, b.w * 64.0f);
    *(uint4*)(g_Wf + i) = make_uint4(
        *reinterpret_cast<uint32_t*>(&h0), *reinterpret_cast<uint32_t*>(&h1),
        *reinterpret_cast<uint32_t*>(&h2), *reinterpret_cast<uint32_t*>(&h3));
}

extern __shared__ __align__(16) char dyn_sm[];

// ---------------------------------------------------------------------------
// Kernel 1: QKV projection, 1-term fp16 (x_f16 * W_f16), 2-stage pipe.
// Outputs: Q,K single fp16; V fp16 hi/lo.  All carry the 64x scale.
// ---------------------------------------------------------------------------
__global__ __launch_bounds__(128, 4) void qkv_mma_kernel()
{
    const int y    = blockIdx.y;
    const int tid  = threadIdx.x;
    const int wid  = tid >> 5;
    const int lane = tid & 31;
    const int m0g  = blockIdx.x * 64;
    const uint32_t smb = smem_to_u32(dyn_sm);

    const char* srcx = (const char*)g_xf;
    const char* srcw = (const char*)(g_Wf + (size_t)y * C * H);

    auto stage = [&](int t) {
        uint32_t base = smb + (t & 1) * QKV_SLOT;
        int k0 = t * 64;
#pragma unroll
        for (int i = 0; i < 8; i++) {
            int within = (i & 3) * 128 + tid;      // 0..511
            const int arr = i >> 2;                // 0=x 1=W
            int r = within >> 3, c = within & 7;
            uint32_t dst = base + arr * TILE_BYTES + r * SKB + c * 16;
            const char* src = (arr == 0)
                ? srcx + ((size_t)(m0g + r) * C + k0 + c * 8) * 2
                : srcw + ((size_t)(k0 + r) * H + c * 8) * 2;
            CP16(dst, src);
        }
        CP_COMMIT();
    };

    float o[8][4];
#pragma unroll
    for (int nt = 0; nt < 8; nt++)
#pragma unroll
        for (int e = 0; e < 4; e++) o[nt][e] = 0.0f;

    const int a_row  = wid * 16 + (lane & 7) + ((lane >> 3) & 1) * 8;
    const int a_colb = (lane >> 4) * 8;
    const int g      = lane >> 3;
    const int t_row  = (lane & 7) + (g & 1) * 8;
    const int t_colb = (g >> 1) * 8;

    const int NT = C / 64;
    stage(0);
    stage(1);

    for (int t = 0; t < NT; t++) {
        if (t + 2 <= NT) CP_WAIT1(); else CP_WAIT0();
        __syncthreads();
        uint32_t bb = smb + (t & 1) * QKV_SLOT;

        uint32_t ax[4][4];
#pragma unroll
        for (int k = 0; k < 4; k++)
            ldsm_x4(ax[k], bb + a_row * SKB + (k * 16 + a_colb) * 2);

#pragma unroll
        for (int np = 0; np < 4; np++) {
#pragma unroll
            for (int k = 0; k < 4; k++) {
                uint32_t bw[4];
                uint32_t ad = (k * 16 + t_row) * SKB + (np * 16 + t_colb) * 2;
                ldsm_x4_t(bw, bb + TILE_BYTES + ad);
                mma16816h(o[2 * np],     ax[k], bw);
                mma16816h(o[2 * np + 1], ax[k], bw + 2);
            }
        }
        __syncthreads();
        if (t + 2 < NT) stage(t + 2);
    }

    const int r0 = m0g + wid * 16 + (lane >> 2);
    if (y < 2) {                        // Q or K: single fp16
        __half* of = (y == 0) ? g_Qf : g_Kf;
#pragma unroll
        for (int nt = 0; nt < 8; nt++) {
            int c = nt * 8 + (lane & 3) * 2;
            __half2 hA = __floats2half2_rn(o[nt][0], o[nt][1]);
            __half2 hB = __floats2half2_rn(o[nt][2], o[nt][3]);
            *(uint32_t*)(of + (size_t)r0 * H + c)       = *reinterpret_cast<uint32_t*>(&hA);
            *(uint32_t*)(of + (size_t)(r0 + 8) * H + c) = *reinterpret_cast<uint32_t*>(&hB);
        }
    } else {                            // V: fp16 hi/lo
#pragma unroll
        for (int nt = 0; nt < 8; nt++) {
            int c = nt * 8 + (lane & 3) * 2;
            uint32_t hi, lo;
            cvt_f16_hilo(o[nt][0], o[nt][1], hi, lo);
            *(uint32_t*)(g_Vhi + (size_t)r0 * H + c) = hi;
            *(uint32_t*)(g_Vlo + (size_t)r0 * H + c) = lo;
            cvt_f16_hilo(o[nt][2], o[nt][3], hi, lo);
            *(uint32_t*)(g_Vhi + (size_t)(r0 + 8) * H + c) = hi;
            *(uint32_t*)(g_Vlo + (size_t)(r0 + 8) * H + c) = lo;
        }
    }
}

// ---------------------------------------------------------------------------
// Kernel 2: flash attention (R15 winner, unchanged).
// S = Qf16 * Kf16 (1-term), PV = Pf16 * (Vhi+Vlo).  2-stage [K|Vhi|Vlo],
// Q frags in registers, 4 CTAs/SM.  grid = (T/64, NCHUNK, BATCH), block 128.
// ---------------------------------------------------------------------------
__global__ __launch_bounds__(128, 4) void flash_mma_kernel()
{
    const int b     = blockIdx.z;
    const int chunk = blockIdx.y;
    const int qt    = blockIdx.x;
    const int tid   = threadIdx.x;
    const int wid   = tid >> 5;
    const int lane  = tid & 31;
    const int q0    = qt * 64;

    const int seg_begin = chunk * CHUNK_KEYS;
    const int seg_end   = min(seg_begin + CHUNK_KEYS, q0 + 64);

    if (seg_begin >= seg_end) {            // chunk beyond causal range
        for (int r = tid; r < 64; r += 128) {
            g_l[((size_t)(b * T) + q0 + r) * NCHUNK + chunk] = 0.0f;
        }
        return;
    }

    const uint32_t smb = smem_to_u32(dyn_sm);
    const int NT = (seg_end - seg_begin + 63) / 64;  // 1..8

    const char* kvsrc[3] = {
        (const char*)g_Kf, (const char*)g_Vhi, (const char*)g_Vlo };

    // stage tile t (K + V hi/lo) into slot t&1
    auto stage = [&](int t) {
        uint32_t base = smb + (t & 1) * KV_SLOT;
        int kt = seg_begin + t * 64;
#pragma unroll
        for (int i = 0; i < 12; i++) {
            int within = (i & 3) * 128 + tid;        // 0..511
            const int arr = i >> 2;                  // 0=K 1=Vhi 2=Vlo
            int r = within >> 3, c = within & 7;
            uint32_t dst = base + arr * TILE_BYTES + r * SKB + c * 16;
            const char* src = kvsrc[arr] + ((size_t)(b * T + kt + r) * H + c * 8) * 2;
            CP16(dst, src);
        }
        CP_COMMIT();
    };

    // ---- Q fragments from global (canonical m16n8k16 A layout, fp16) ----
    uint32_t qf[4][4];
    {
        const int rl = wid * 16 + (lane >> 2);
        const int tg = lane & 3;
        const uint32_t* Q32 = (const uint32_t*)(g_Qf + (size_t)(b * T + q0) * H);
#pragma unroll
        for (int k = 0; k < 4; k++) {
            int cb = k * 8 + tg;                     // uint32 col of 32/row
            qf[k][0] = Q32[(size_t)rl * 32 + cb];
            qf[k][1] = Q32[(size_t)(rl + 8) * 32 + cb];
            qf[k][2] = Q32[(size_t)rl * 32 + cb + 4];
            qf[k][3] = Q32[(size_t)(rl + 8) * 32 + cb + 4];
        }
    }

    stage(0);
    if (NT > 1) stage(1);

    const int g      = lane >> 3;
    const int nt_row = (lane & 7) + (g >> 1) * 8;   // K non-trans B-frag
    const int nt_colb = (g & 1) * 8;
    const int t_row  = (lane & 7) + (g & 1) * 8;    // V trans B-frag
    const int t_colb = (g >> 1) * 8;

    float o[8][4];
#pragma unroll
    for (int nt = 0; nt < 8; nt++)
#pragma unroll
        for (int e = 0; e < 4; e++) o[nt][e] = 0.0f;
    float l0 = 0.0f, l1 = 0.0f;

    const int row_i0 = (wid << 4) + (lane >> 2);

    for (int t = 0; t < NT; t++) {
        if (t + 2 <= NT) CP_WAIT1(); else CP_WAIT0();
        __syncthreads();
        const uint32_t kb = smb + (t & 1) * KV_SLOT;
        const uint32_t vb = kb + TILE_BYTES;
        const int kt = seg_begin + t * 64;

        // ---- S = Q K (single-term fp16) ----
        float s[8][4];
#pragma unroll
        for (int nt = 0; nt < 8; nt++)
#pragma unroll
            for (int e = 0; e < 4; e++) s[nt][e] = 0.0f;

#pragma unroll
        for (int k = 0; k < 4; k++) {
#pragma unroll
            for (int np = 0; np < 4; np++) {
                uint32_t bk[4];
                uint32_t ad = (np * 16 + nt_row) * SKB + (k * 16 + nt_colb) * 2;
                ldsm_x4(bk, kb + ad);
                mma16816h(s[2 * np],     qf[k], bk);
                mma16816h(s[2 * np + 1], qf[k], bk + 2);
            }
        }

        // ---- softmax numerator: p = exp2(v), no max-subtraction needed ----
        const bool needmask = (kt + 63 > q0 + (wid << 4));
        float ls0 = 0.0f, ls1 = 0.0f;
#pragma unroll
        for (int nt = 0; nt < 8; nt++) {
#pragma unroll
            for (int e = 0; e < 4; e++) {
                float v = s[nt][e] * SC2;
                if (needmask) {
                    int j = kt + nt * 8 + (lane & 3) * 2 + (e & 1);
                    int i = q0 + row_i0 + (e >> 1) * 8;
                    if (j > i) v = -INFINITY;   // exp2 -> 0
                }
                s[nt][e] = exp2f(v);
            }
            ls0 += s[nt][0] + s[nt][1];
            ls1 += s[nt][2] + s[nt][3];
        }
        l0 += ls0;
        l1 += ls1;

        // ---- O += P (Vhi + Vlo)  (2-term fp16) ----
#pragma unroll
        for (int k = 0; k < 4; k++) {
            uint32_t aP[4];
#pragma unroll
            for (int h = 0; h < 2; h++) {
                int nt = 2 * k + h;
                __half2 pA = __floats2half2_rn(s[nt][0], s[nt][1]);
                __half2 pB = __floats2half2_rn(s[nt][2], s[nt][3]);
                aP[h * 2 + 0] = *reinterpret_cast<uint32_t*>(&pA);
                aP[h * 2 + 1] = *reinterpret_cast<uint32_t*>(&pB);
            }
#pragma unroll
            for (int dp = 0; dp < 4; dp++) {
                uint32_t bh[4], bl[4];
                uint32_t ad = (k * 16 + t_row) * SKB + (dp * 16 + t_colb) * 2;
                ldsm_x4_t(bh, vb + ad);
                ldsm_x4_t(bl, vb + TILE_BYTES + ad);
                mma16816h(o[2 * dp],     aP, bh);
                mma16816h(o[2 * dp + 1], aP, bh + 2);
                mma16816h(o[2 * dp],     aP, bl);
                mma16816h(o[2 * dp + 1], aP, bl + 2);
            }
        }

        __syncthreads();                  // all reads of slot (t&1) done
        if (t + 2 < NT) stage(t + 2);     // refill freed slot
    }

    // per-row quad sum of l
    l0 += __shfl_xor_sync(0xFFFFFFFFu, l0, 1);
    l0 += __shfl_xor_sync(0xFFFFFFFFu, l0, 2);
    l1 += __shfl_xor_sync(0xFFFFFFFFu, l1, 1);
    l1 += __shfl_xor_sync(0xFFFFFFFFu, l1, 2);

    // ---- write chunk partials (fp32; o carries the 64x V scale) ----
    const int r0g = q0 + row_i0;
    const size_t pb0 = ((size_t)(b * T) + r0g) * NCHUNK + chunk;
    const size_t pb1 = ((size_t)(b * T) + r0g + 8) * NCHUNK + chunk;
#pragma unroll
    for (int nt = 0; nt < 8; nt++) {
        int c = nt * 8 + (lane & 3) * 2;
        *(float2*)&g_acc[pb0 * H + c] = make_float2(o[nt][0], o[nt][1]);
        *(float2*)&g_acc[pb1 * H + c] = make_float2(o[nt][2], o[nt][3]);
    }
    if ((lane & 3) == 0) {
        g_l[pb0] = l0;
        g_l[pb1] = l1;
    }
}

// ---------------------------------------------------------------------------
// Kernel 3: combine chunk partials: plain sums (weights are all 1).
// Skip l==0 chunks (covers never-launched chunks whose acc is garbage).
// ---------------------------------------------------------------------------
__global__ __launch_bounds__(256) void combine_kernel(float* __restrict__ out)
{
    int idx   = blockIdx.x * 256 + threadIdx.x;
    int d     = idx & (H - 1);
    int query = idx >> 6;

    float L = 0.0f, o = 0.0f;
#pragma unroll
    for (int i = 0; i < NCHUNK; i++) {
        float li = g_l[(size_t)query * NCHUNK + i];
        if (li > 0.0f) {
            L += li;
            o += g_acc[((size_t)query * NCHUNK + i) * H + d];
        }
    }
    out[idx] = o * INV_VSCALE / L;
}

// ---------------------------------------------------------------------------
extern "C" void kernel_launch(void* const* d_in, const int* in_sizes, int n_in,
                              void* d_out, int out_size)
{
    const float* x  = (const float*)d_in[0];
    const float* Wq = (const float*)d_in[1];
    const float* Wk = (const float*)d_in[2];
    const float* Wv = (const float*)d_in[3];
    float* out = (float*)d_out;

    // host-side, idempotent, capture-safe
    cudaFuncSetAttribute(qkv_mma_kernel,
        cudaFuncAttributeMaxDynamicSharedMemorySize, QKV_SMEM);
    cudaFuncSetAttribute(flash_mma_kernel,
        cudaFuncAttributeMaxDynamicSharedMemorySize, FLASH_SMEM);

    prep_x_kernel<<<(size_t)M_TOT * C / 2048, 256>>>(x);
    prep_w_kernel<<<3 * C * H / 2048, 256>>>(Wq, Wk, Wv);
    qkv_mma_kernel<<<dim3(M_TOT / 64, 3), 128, QKV_SMEM>>>();
    flash_mma_kernel<<<dim3(T / 64, NCHUNK, BATCH), 128, FLASH_SMEM>>>();
    combine_kernel<<<(M_TOT * H) / 256, 256>>>(out);
}